// round 16
// baseline (speedup 1.0000x reference)
#include <cuda_runtime.h>
#include <cstdint>

#define HW      262144          // 512*512 = 2^18
#define BSZ     64
#define CC      3
#define NU      (BSZ*HW)        // 16777216 uniforms (mask domain)
#define NX      (BSZ*CC*HW)     // 50331648 x elements
#define KKEEP   183500          // int(262144*0.7)
#define CAP     12288           // candidate capacity per row (expected ~8192)
#define SEG     32              // gen blocks per row
#define SBUF    640             // per-block staging (expected 256, ~24 sigma)
// Fixed selection window around expected k-th key (0.7*2^23 ~ 5872026).
// Rank sigma ~235 elems ~ 7500 key units; +-131072 ~ 17 sigma.
#define T_LO    5740928u
#define T_HI    6003072u

// ---------------- static device scratch (no allocation allowed) -------------
__device__ uint32_t           g_m[NU];               // cached 23-bit uniform keys
__device__ uint32_t           g_below[BSZ];          // exact count of m < T_LO
__device__ unsigned long long g_pairs[BSZ][CAP];     // window candidates (m<<18|col)
__device__ uint32_t           g_cnt[BSZ];
__device__ uint32_t           g_thresh[BSZ];
__device__ uint32_t           g_tiecols[BSZ][64];
__device__ uint32_t           g_ntk[BSZ];

// ---------------- Threefry-2x32 (20 rounds), matches jax._src.prng ----------
// rotIM: rotate via 32x32->64 multiply by runtime-opaque 2^r (kernel arg) ->
//        IMAD.WIDE on the fma pipe + one LOP3 for (lo|hi)^x0.
__device__ __forceinline__ uint32_t rotIM(uint32_t v, uint32_t pw) {
    unsigned long long p = (unsigned long long)v * pw;   // pw = 2^r (opaque)
    return (uint32_t)p | (uint32_t)(p >> 32);
}

// host reference version (key derivation on host)
__host__ __device__ __forceinline__
void tf2x32_h(uint32_t k0, uint32_t k1, uint32_t x0, uint32_t x1,
              uint32_t &o0, uint32_t &o1) {
    uint32_t ks2 = k0 ^ k1 ^ 0x1BD11BDAu;
#define TFRH(r) { x0 += x1; x1 = ((x1 << (r)) | (x1 >> (32 - (r)))) ^ x0; }
    x0 += k0;  x1 += k1;
    TFRH(13) TFRH(15) TFRH(26) TFRH(6)
    x0 += k1;  x1 += ks2 + 1u;
    TFRH(17) TFRH(29) TFRH(16) TFRH(24)
    x0 += ks2; x1 += k0 + 2u;
    TFRH(13) TFRH(15) TFRH(26) TFRH(6)
    x0 += k0;  x1 += k1 + 3u;
    TFRH(17) TFRH(29) TFRH(16) TFRH(24)
    x0 += k1;  x1 += ks2 + 4u;
    TFRH(13) TFRH(15) TFRH(26) TFRH(6)
    x0 += ks2; x1 += k0 + 5u;
#undef TFRH
    o0 = x0; o1 = x1;
}

// 4-way interleaved threefry: all-IMAD rotations, 4 independent chains.
// Produces bits for counters gi, gi+1, gi+2, gi+3.
#define R4(pw)  { _Pragma("unroll") for (int j = 0; j < 4; j++) {            \
                    a0[j] += a1[j]; a1[j] = rotIM(a1[j], (pw)) ^ a0[j]; } }
#define KI4(a,b){ _Pragma("unroll") for (int j = 0; j < 4; j++) {            \
                    a0[j] += (a); a1[j] += (b); } }

__device__ __forceinline__
void rbits4(uint32_t k0, uint32_t k1, uint32_t ks2, uint32_t gi,
            uint4 pw0, uint4 pw1, uint32_t* bits) {
    uint32_t a0[4], a1[4];
#pragma unroll
    for (int j = 0; j < 4; j++) { a0[j] = k0; a1[j] = gi + (uint32_t)j + k1; }
    R4(pw0.x) R4(pw0.y) R4(pw0.z) R4(pw0.w)
    KI4(k1, ks2 + 1u)
    R4(pw1.x) R4(pw1.y) R4(pw1.z) R4(pw1.w)
    KI4(ks2, k0 + 2u)
    R4(pw0.x) R4(pw0.y) R4(pw0.z) R4(pw0.w)
    KI4(k0, k1 + 3u)
    R4(pw1.x) R4(pw1.y) R4(pw1.z) R4(pw1.w)
    KI4(k1, ks2 + 4u)
    R4(pw0.x) R4(pw0.y) R4(pw0.z) R4(pw0.w)
    KI4(ks2, k0 + 5u)
#pragma unroll
    for (int j = 0; j < 4; j++) bits[j] = a0[j] ^ a1[j];
}

// XLA ErfInv (fp32, Giles polynomial)
__device__ __forceinline__ float erfinv_f(float x) {
    float w = -__logf((1.0f - x) * (1.0f + x));
    float p;
    if (w < 5.0f) {
        w -= 2.5f;
        p =               2.81022636e-08f;
        p = fmaf(p, w,    3.43273939e-07f);
        p = fmaf(p, w,   -3.5233877e-06f);
        p = fmaf(p, w,   -4.39150654e-06f);
        p = fmaf(p, w,    0.00021858087f);
        p = fmaf(p, w,   -0.00125372503f);
        p = fmaf(p, w,   -0.00417768164f);
        p = fmaf(p, w,    0.246640727f);
        p = fmaf(p, w,    1.50140941f);
    } else {
        w = sqrtf(w) - 3.0f;
        p =              -0.000200214257f;
        p = fmaf(p, w,    0.000100950558f);
        p = fmaf(p, w,    0.00134934322f);
        p = fmaf(p, w,   -0.00367342844f);
        p = fmaf(p, w,    0.00573950773f);
        p = fmaf(p, w,   -0.0076224613f);
        p = fmaf(p, w,    0.00943887047f);
        p = fmaf(p, w,    1.00167406f);
        p = fmaf(p, w,    2.83297682f);
    }
    return p * x;
}

// 4 noise factors (1 + 0.1*N(0,1)) for counters gi..gi+3, 4-way ILP
__device__ __forceinline__
void noise4_f(uint32_t nk0, uint32_t nk1, uint32_t ks2, uint32_t gi,
              uint4 pw0, uint4 pw1, float* nn) {
    uint32_t bits[4];
    rbits4(nk0, nk1, ks2, gi, pw0, pw1, bits);
#pragma unroll
    for (int j = 0; j < 4; j++) {
        float f = __uint_as_float((bits[j] >> 9) | 0x3F800000u) - 1.0f;
        float u = fmaxf(f * 2.0f + (-0.99999994f), -0.99999994f);
        nn[j] = fmaf(1.4142135623730951f * erfinv_f(u), 0.1f, 1.0f);
    }
}

// ---------------- kernels ----------------------------------------------------
__global__ void k_init() {
    uint32_t i = threadIdx.x;
    if (i < BSZ) { g_cnt[i] = 0u; g_ntk[i] = 0u; g_below[i] = 0u; }
}

// Generate keys (4-way ILP), cache m=bits>>9, exact count of m<T_LO,
// window candidates staged in SHARED, one global atomic per block.
__global__ void __launch_bounds__(256, 3)
k_gen(uint32_t mk0, uint32_t mk1, uint4 pw0, uint4 pw1) {
    __shared__ unsigned long long s_buf[SBUF];
    __shared__ uint32_t s_cnt;
    __shared__ uint32_t s_base;
    if (threadIdx.x == 0) s_cnt = 0u;
    __syncthreads();

    uint32_t ks2  = mk0 ^ mk1 ^ 0x1BD11BDAu;
    uint32_t row  = blockIdx.x / SEG;
    uint32_t seg  = blockIdx.x % SEG;
    uint32_t base = row * HW + seg * (HW / SEG);
    uint32_t cntlo = 0;
#pragma unroll 2
    for (int it = 0; it < (HW / SEG) / 1024; it++) {
        // 4 chains: strided by 256 so each store stays fully coalesced
        uint32_t i0 = base + it * 1024 + threadIdx.x;
        uint32_t bA, bB, bC, bD;
        {   // indices i0, i0+256, i0+512, i0+768 are NOT consecutive counters,
            // so run 4 chains with explicit counter init (reuse rbits4 pattern)
            uint32_t a0[4], a1[4];
#pragma unroll
            for (int j = 0; j < 4; j++) { a0[j] = mk0; a1[j] = (i0 + 256u * j) + mk1; }
            R4(pw0.x) R4(pw0.y) R4(pw0.z) R4(pw0.w)
            KI4(mk1, ks2 + 1u)
            R4(pw1.x) R4(pw1.y) R4(pw1.z) R4(pw1.w)
            KI4(ks2, mk0 + 2u)
            R4(pw0.x) R4(pw0.y) R4(pw0.z) R4(pw0.w)
            KI4(mk0, mk1 + 3u)
            R4(pw1.x) R4(pw1.y) R4(pw1.z) R4(pw1.w)
            KI4(mk1, ks2 + 4u)
            R4(pw0.x) R4(pw0.y) R4(pw0.z) R4(pw0.w)
            KI4(ks2, mk0 + 5u)
            bA = a0[0] ^ a1[0]; bB = a0[1] ^ a1[1];
            bC = a0[2] ^ a1[2]; bD = a0[3] ^ a1[3];
        }
        uint32_t mm[4] = { bA >> 9, bB >> 9, bC >> 9, bD >> 9 };
#pragma unroll
        for (int j = 0; j < 4; j++) {
            uint32_t i = i0 + 256u * j;
            g_m[i] = mm[j];
            cntlo += (mm[j] < T_LO) ? 1u : 0u;
            if (mm[j] >= T_LO && mm[j] < T_HI) {
                uint32_t pos = atomicAdd(&s_cnt, 1u);
                if (pos < SBUF)
                    s_buf[pos] = (((unsigned long long)mm[j]) << 18) | (i & 0x3FFFFu);
            }
        }
    }
    // warp reduce + one atomic per warp (below-window exact count)
    cntlo += __shfl_xor_sync(0xffffffffu, cntlo, 16);
    cntlo += __shfl_xor_sync(0xffffffffu, cntlo, 8);
    cntlo += __shfl_xor_sync(0xffffffffu, cntlo, 4);
    cntlo += __shfl_xor_sync(0xffffffffu, cntlo, 2);
    cntlo += __shfl_xor_sync(0xffffffffu, cntlo, 1);
    if ((threadIdx.x & 31u) == 0u) atomicAdd(&g_below[row], cntlo);

    __syncthreads();
    uint32_t n = min(s_cnt, (uint32_t)SBUF);
    if (threadIdx.x == 0) s_base = atomicAdd(&g_cnt[row], n);
    __syncthreads();
    uint32_t gb = s_base;
    for (uint32_t j = threadIdx.x; j < n; j += 256)
        if (gb + j < CAP) g_pairs[row][gb + j] = s_buf[j];
}

// One block per row: exact k-th key + stable (index-ordered) tie set,
// via 1024-bucket mini-histogram over the ~8192 window candidates.
__global__ void __launch_bounds__(256)
k_sel() {
    int row = blockIdx.x;
    __shared__ uint32_t hist2[1024];
    __shared__ unsigned long long sp2[256];
    __shared__ uint32_t sn2, sB2, sR2, sT;
    for (int j = threadIdx.x; j < 1024; j += 256) hist2[j] = 0u;
    if (threadIdx.x == 0) sn2 = 0u;
    __syncthreads();

    uint32_t n = min(g_cnt[row], (uint32_t)CAP);
    for (uint32_t j = threadIdx.x; j < n; j += 256) {
        uint32_t m = (uint32_t)(g_pairs[row][j] >> 18);
        atomicAdd(&hist2[(m - T_LO) >> 8], 1u);
    }
    __syncthreads();

    if (threadIdx.x == 0) {
        uint32_t r = (uint32_t)KKEEP - g_below[row];  // 1-indexed rank among candidates
        uint32_t cum = 0, B2 = 0;
        for (int b = 0; b < 1024; b++) {
            uint32_t h = hist2[b];
            if (cum + h >= r) { B2 = (uint32_t)b; break; }
            cum += h;
        }
        sB2 = B2; sR2 = r - cum;                      // 1-indexed within bucket
    }
    __syncthreads();

    uint32_t B2 = sB2, r2 = sR2;
    for (uint32_t j = threadIdx.x; j < n; j += 256) {
        unsigned long long v = g_pairs[row][j];
        uint32_t m = (uint32_t)(v >> 18);
        if (((m - T_LO) >> 8) == B2) {
            uint32_t pos = atomicAdd(&sn2, 1u);
            if (pos < 256u) sp2[pos] = v;
        }
    }
    __syncthreads();

    uint32_t n2 = min(sn2, 256u);
    for (uint32_t j = threadIdx.x; j < n2; j += 256) {
        unsigned long long v = sp2[j];
        uint32_t rk = 0;
        for (uint32_t l = 0; l < n2; l++) rk += (sp2[l] < v) ? 1u : 0u;
        if (rk == r2 - 1u) sT = (uint32_t)(v >> 18);
    }
    __syncthreads();

    uint32_t T = sT;
    if (threadIdx.x == 0) g_thresh[row] = T;
    for (uint32_t j = threadIdx.x; j < n2; j += 256) {
        unsigned long long v = sp2[j];
        if ((uint32_t)(v >> 18) == T) {
            uint32_t rk = 0;
            for (uint32_t l = 0; l < n2; l++) rk += (sp2[l] < v) ? 1u : 0u;
            if (rk < r2) {
                uint32_t pos = atomicAdd(&g_ntk[row], 1u);
                if (pos < 64u) g_tiecols[row][pos] = (uint32_t)(v & 0x3FFFFu);
            }
        }
    }
}

// Fused: per pixel-quad -> mask (write) + all 3 channels of out (4-way ILP noise)
__global__ void __launch_bounds__(256, 3)
k_out_fused(const float4* __restrict__ x, float4* __restrict__ out,
            float4* __restrict__ maskout, uint32_t nk0, uint32_t nk1,
            uint4 pw0, uint4 pw1) {
    uint32_t q   = blockIdx.x * blockDim.x + threadIdx.x;  // [0, NU/4)
    uint32_t pix = q * 4u;
    uint32_t b   = pix >> 18;
    uint32_t p   = pix & 0x3FFFFu;
    uint32_t T   = g_thresh[b];
    uint32_t ks2 = nk0 ^ nk1 ^ 0x1BD11BDAu;

    uint4 mq = reinterpret_cast<const uint4*>(g_m)[q];
    uint32_t ms[4] = {mq.x, mq.y, mq.z, mq.w};
    float mk[4];
    bool anytie = (ms[0] == T) | (ms[1] == T) | (ms[2] == T) | (ms[3] == T);
#pragma unroll
    for (int j = 0; j < 4; j++) mk[j] = (ms[j] < T) ? 1.0f : 0.0f;
    if (anytie) {
        uint32_t ntk = g_ntk[b];
#pragma unroll
        for (int j = 0; j < 4; j++) {
            if (ms[j] == T) {
                uint32_t col = p + (uint32_t)j;
                for (uint32_t t = 0; t < ntk; t++)
                    if (g_tiecols[b][t] == col) mk[j] = 1.0f;
            }
        }
    }
    maskout[q] = make_float4(mk[0], mk[1], mk[2], mk[3]);

    uint32_t gibase = (b * 3u) * (uint32_t)HW + p;   // channel 0 element index
#pragma unroll
    for (int c = 0; c < 3; c++) {
        uint32_t gi = gibase + (uint32_t)c * (uint32_t)HW;
        float4 xv = x[gi >> 2];
        float nn[4];
        noise4_f(nk0, nk1, ks2, gi, pw0, pw1, nn);
        float4 o;
        o.x = xv.x * mk[0] * nn[0];
        o.y = xv.y * mk[1] * nn[1];
        o.z = xv.z * mk[2] * nn[2];
        o.w = xv.w * mk[3] * nn[3];
        out[gi >> 2] = o;
    }
}

// ---------------- launch ------------------------------------------------------
extern "C" void kernel_launch(void* const* d_in, const int* in_sizes, int n_in,
                              void* d_out, int out_size) {
    const float* x   = (const float*)d_in[0];
    float* out       = (float*)d_out;
    float* maskout   = out + NX;          // output layout: [x (NX) | mask (NU)]

    // jax.random.key(42) -> (0,42); partitionable fold-like split:
    uint32_t mk0, mk1, nk0, nk1;
    tf2x32_h(0u, 42u, 0u, 0u, mk0, mk1);    // k_mask
    tf2x32_h(0u, 42u, 0u, 1u, nk0, nk1);    // k_noise

    // rotation powers, passed as runtime args so ptxas emits IMAD.WIDE
    uint4 pw0 = make_uint4(1u << 13, 1u << 15, 1u << 26, 1u << 6);
    uint4 pw1 = make_uint4(1u << 17, 1u << 29, 1u << 16, 1u << 24);

    k_init     <<<1, 64>>>();
    k_gen      <<<BSZ * SEG, 256>>>(mk0, mk1, pw0, pw1);
    k_sel      <<<BSZ, 256>>>();
    k_out_fused<<<(NU / 4) / 256, 256>>>((const float4*)x, (float4*)out,
                                         (float4*)maskout, nk0, nk1, pw0, pw1);
}